// round 9
// baseline (speedup 1.0000x reference)
#include <cuda_runtime.h>
#include <cuda_bf16.h>
#include <cstdint>

#define HID   1024
#define NH    16
#define DK    64
#define BATCH 4
#define SEQ   2048
#define MTOT  (BATCH*SEQ)

// ---- mma.sync / ldmatrix / cp.async helpers (base compute_100 features) ----
__device__ __forceinline__ uint32_t smem_to_u32(const void* p) {
    uint32_t a;
    asm("{ .reg .u64 t; cvta.to.shared.u64 t, %1; cvt.u32.u64 %0, t; }" : "=r"(a) : "l"(p));
    return a;
}
#define LDSM4(r0, r1, r2, r3, addr) \
    asm volatile("ldmatrix.sync.aligned.m8n8.x4.shared.b16 {%0,%1,%2,%3},[%4];" \
        : "=r"(r0), "=r"(r1), "=r"(r2), "=r"(r3) : "r"(addr))
#define LDSM4T(r0, r1, r2, r3, addr) \
    asm volatile("ldmatrix.sync.aligned.m8n8.x4.trans.shared.b16 {%0,%1,%2,%3},[%4];" \
        : "=r"(r0), "=r"(r1), "=r"(r2), "=r"(r3) : "r"(addr))
#define MMA16816(c, a, b) \
    asm volatile("mma.sync.aligned.m16n8k16.row.col.f32.bf16.bf16.f32 " \
        "{%0,%1,%2,%3},{%4,%5,%6,%7},{%8,%9},{%0,%1,%2,%3};" \
        : "+f"((c)[0]), "+f"((c)[1]), "+f"((c)[2]), "+f"((c)[3]) \
        : "r"((a)[0]), "r"((a)[1]), "r"((a)[2]), "r"((a)[3]), "r"((b)[0]), "r"((b)[1]))
#define CP_ASYNC16(dst, src) \
    asm volatile("cp.async.ca.shared.global [%0], [%1], 16;" :: "r"(dst), "l"(src) : "memory")
#define CP_COMMIT()  asm volatile("cp.async.commit_group;" ::: "memory")
#define CP_WAIT0()   asm volatile("cp.async.wait_group 0;" ::: "memory")

// bf16 2-term split helpers
__device__ __forceinline__ void bf16split(float x, __nv_bfloat16& h, __nv_bfloat16& l) {
    h = __float2bfloat16_rn(x);
    l = __float2bfloat16_rn(x - __bfloat162float(h));
}
__device__ __forceinline__ uint32_t pkbf(__nv_bfloat16 a, __nv_bfloat16 b) {
    __nv_bfloat162 t(a, b);
    return *(uint32_t*)&t;
}
__device__ __forceinline__ void pk2split(float x, float y, uint32_t& h, uint32_t& l) {
    __nv_bfloat16 hx, lx, hy, ly;
    bf16split(x, hx, lx); bf16split(y, hy, ly);
    h = pkbf(hx, hy); l = pkbf(lx, ly);
}

// Scratch (allocation-free rule: __device__ globals)
__device__ float g_q[(size_t)BATCH*NH*SEQ*DK];      // fp32, pre-scaled by 1/8
__device__ __nv_bfloat16 g_kh[(size_t)BATCH*NH*SEQ*DK];  // pre-split K hi plane
__device__ __nv_bfloat16 g_kl[(size_t)BATCH*NH*SEQ*DK];  // K lo plane
__device__ __nv_bfloat16 g_vh[(size_t)BATCH*NH*SEQ*DK];
__device__ __nv_bfloat16 g_vl[(size_t)BATCH*NH*SEQ*DK];
__device__ float g_ctx[(size_t)MTOT*HID];

// ---------------------------------------------------------------------------
// bf16-split tensor-core GEMM: Y = X W^T + bias
// Thread-per-row staging with STS.128 split stores.
// MODE 0, z=0: -> g_q (fp32, scaled); z=1: -> g_kh/g_kl; z=2: -> g_vh/g_vl
// MODE 1: g_ctx -> OutPlain
// ---------------------------------------------------------------------------
#define BK      32
#define NKT     (HID / BK)
#define KPAD    40
#define PLANE   (128 * KPAD)
#define STG     (4 * PLANE)
#define GEMM_SMEM (2 * STG * 2)

template<int MODE>
__global__ __launch_bounds__(256)
void gemm_mma(const float* __restrict__ Xin,
              const float* __restrict__ W0, const float* __restrict__ B0,
              const float* __restrict__ W1, const float* __restrict__ B1,
              const float* __restrict__ W2, const float* __restrict__ B2,
              float* __restrict__ OutPlain)
{
    extern __shared__ __nv_bfloat16 sm[];
    const uint32_t smb = smem_to_u32(sm);

    const float* X = (MODE == 1) ? g_ctx : Xin;
    const int z = blockIdx.z;
    const float* W;
    const float* bias;
    if (MODE == 0) {
        W    = (z == 0) ? W0 : ((z == 1) ? W1 : W2);
        bias = (z == 0) ? B0 : ((z == 1) ? B1 : B2);
    } else {
        W = W0; bias = B0;
    }

    const int m0   = blockIdx.x * 128;
    const int n0   = blockIdx.y * 128;
    const int tid  = threadIdx.x;
    const int wid  = tid >> 5;
    const int lane = tid & 31;
    const int warp_m = (wid >> 2) * 64;
    const int warp_n = (wid & 3) * 32;

    // staging: thread = one full 32-float row slice of A (tid<128) or B (tid>=128)
    const bool isB = tid >= 128;
    const int  row = tid & 127;
    const float* src0 = isB ? (W + (size_t)(n0 + row) * HID)
                            : (X + (size_t)(m0 + row) * HID);

    float4 rr[8];
    auto G2R = [&](int kt) {
        const float* s = src0 + kt * BK;
#pragma unroll
        for (int i = 0; i < 8; i++) rr[i] = *(const float4*)(s + i * 4);
    };
    auto R2S = [&](int s) {
        __nv_bfloat16* hp = sm + s * STG + (isB ? 2 : 0) * PLANE + row * KPAD;
        __nv_bfloat16* lp = hp + PLANE;
#pragma unroll
        for (int i = 0; i < 4; i++) {
            const float4 a = rr[2 * i], b = rr[2 * i + 1];
            uint4 hv, lv;
            pk2split(a.x, a.y, hv.x, lv.x);
            pk2split(a.z, a.w, hv.y, lv.y);
            pk2split(b.x, b.y, hv.z, lv.z);
            pk2split(b.z, b.w, hv.w, lv.w);
            *(uint4*)(hp + i * 8) = hv;
            *(uint4*)(lp + i * 8) = lv;
        }
    };

    float acc[4][4][4];
#pragma unroll
    for (int mt = 0; mt < 4; mt++)
#pragma unroll
        for (int nt = 0; nt < 4; nt++)
#pragma unroll
            for (int e = 0; e < 4; e++) acc[mt][nt][e] = 0.f;

    const int arow = warp_m + (lane & 15);
    const int acolL = (lane >> 4) * 8;
    const int brow = warp_n + ((lane >> 4) & 1) * 8 + (lane & 7);
    const int bcolL = ((lane >> 3) & 1) * 8;

    G2R(0); R2S(0);
    __syncthreads();

    for (int kt = 0; kt < NKT; kt++) {
        const int s = kt & 1;
        if (kt + 1 < NKT) G2R(kt + 1);

        const uint32_t sb = smb + (uint32_t)(s * STG) * 2;
        uint32_t ahi[4][4], alo[4][4], bhi[4][2], blo[4][2];
#pragma unroll
        for (int sub = 0; sub < 2; sub++) {
            const int kks = sub * 16;
#pragma unroll
            for (int mt = 0; mt < 4; mt++) {
                uint32_t ad = sb + (uint32_t)(((arow + mt * 16) * KPAD) + kks + acolL) * 2;
                LDSM4(ahi[mt][0], ahi[mt][1], ahi[mt][2], ahi[mt][3], ad);
                LDSM4(alo[mt][0], alo[mt][1], alo[mt][2], alo[mt][3], ad + PLANE * 2);
            }
#pragma unroll
            for (int p = 0; p < 2; p++) {
                uint32_t bd = sb + (uint32_t)(2 * PLANE + ((brow + p * 16) * KPAD) + kks + bcolL) * 2;
                LDSM4(bhi[2*p][0], bhi[2*p][1], bhi[2*p+1][0], bhi[2*p+1][1], bd);
                LDSM4(blo[2*p][0], blo[2*p][1], blo[2*p+1][0], blo[2*p+1][1], bd + PLANE * 2);
            }
#pragma unroll
            for (int mt = 0; mt < 4; mt++)
#pragma unroll
                for (int nt = 0; nt < 4; nt++) {
                    MMA16816(acc[mt][nt], ahi[mt], bhi[nt]);
                    MMA16816(acc[mt][nt], ahi[mt], blo[nt]);
                    MMA16816(acc[mt][nt], alo[mt], bhi[nt]);
                }
        }

        if (kt + 1 < NKT) R2S((kt + 1) & 1);
        __syncthreads();
    }

    const int g  = lane >> 2;
    const int tg = lane & 3;
#pragma unroll
    for (int mt = 0; mt < 4; mt++) {
        const int m1 = m0 + warp_m + mt * 16 + g;
        const int m2 = m1 + 8;
#pragma unroll
        for (int nt = 0; nt < 4; nt++) {
            const int n = n0 + warp_n + nt * 8 + tg * 2;
            const float bv0 = __ldg(bias + n);
            const float bv1 = __ldg(bias + n + 1);
            const float* c = acc[mt][nt];
            if (MODE == 0) {
                const int hh = n >> 6, d = n & 63;
                const size_t i1 = (((size_t)((m1 >> 11) * NH + hh)) * SEQ + (m1 & 2047)) * DK + d;
                const size_t i2 = (((size_t)((m2 >> 11) * NH + hh)) * SEQ + (m2 & 2047)) * DK + d;
                const float v0 = c[0] + bv0, v1 = c[1] + bv1;
                const float v2 = c[2] + bv0, v3 = c[3] + bv1;
                if (z == 0) {
                    *(float2*)(g_q + i1) = make_float2(v0 * 0.125f, v1 * 0.125f);
                    *(float2*)(g_q + i2) = make_float2(v2 * 0.125f, v3 * 0.125f);
                } else {
                    __nv_bfloat16* ph = (z == 1) ? g_kh : g_vh;
                    __nv_bfloat16* pl = (z == 1) ? g_kl : g_vl;
                    __nv_bfloat16 h0, l0, h1, l1;
                    bf16split(v0, h0, l0); bf16split(v1, h1, l1);
                    *(__nv_bfloat162*)(ph + i1) = __nv_bfloat162(h0, h1);
                    *(__nv_bfloat162*)(pl + i1) = __nv_bfloat162(l0, l1);
                    bf16split(v2, h0, l0); bf16split(v3, h1, l1);
                    *(__nv_bfloat162*)(ph + i2) = __nv_bfloat162(h0, h1);
                    *(__nv_bfloat162*)(pl + i2) = __nv_bfloat162(l0, l1);
                }
            } else {
                *(float2*)(OutPlain + (size_t)m1 * HID + n) = make_float2(c[0] + bv0, c[1] + bv1);
                *(float2*)(OutPlain + (size_t)m2 * HID + n) = make_float2(c[2] + bv0, c[3] + bv1);
            }
        }
    }
}

// ---------------------------------------------------------------------------
// Flash attention on tensor cores. K/V pre-split bf16 hi/lo in gmem;
// staged via double-buffered cp.async (no conversion in the loop).
// CTA: 128 queries, 8 warps (16 rows each). Key chunks of 64.
// ---------------------------------------------------------------------------
#define SC    64
#define QB    128
#define DPAD  72                   // 144B rows: conflict-free ldmatrix + 16B aligned
#define PLB   (SC * DPAD * 2)      // plane bytes = 9216
#define ATTN_SMEM (2 * 4 * PLB)    // 2 stages x 4 planes = 73728

__global__ __launch_bounds__(256)
void attn_mma()
{
    extern __shared__ __nv_bfloat16 asmem[];
    const uint32_t smBase = smem_to_u32(asmem);

    const int b    = blockIdx.z;
    const int h    = blockIdx.y;
    const int tid  = threadIdx.x;
    const int wid  = tid >> 5;
    const int lane = tid & 31;
    const int g    = lane >> 2;
    const int tg   = lane & 3;

    const size_t bh = (size_t)(b * NH + h);
    const size_t bhoff = bh * SEQ * DK;
    const int qrow0 = blockIdx.x * QB + wid * 16;

    // ---- Q a-frags (hi/lo) from fp32 gmem, loaded once ----
    uint32_t qa_h[4][4], qa_l[4][4];
    {
        const float* q0 = g_q + (bh * SEQ + qrow0 + g) * DK;
        const float* q8 = q0 + 8 * DK;
#pragma unroll
        for (int kk = 0; kk < 4; kk++) {
            float2 v;
            v = *(const float2*)(q0 + kk * 16 + 2 * tg);
            pk2split(v.x, v.y, qa_h[kk][0], qa_l[kk][0]);
            v = *(const float2*)(q8 + kk * 16 + 2 * tg);
            pk2split(v.x, v.y, qa_h[kk][1], qa_l[kk][1]);
            v = *(const float2*)(q0 + kk * 16 + 8 + 2 * tg);
            pk2split(v.x, v.y, qa_h[kk][2], qa_l[kk][2]);
            v = *(const float2*)(q8 + kk * 16 + 8 + 2 * tg);
            pk2split(v.x, v.y, qa_h[kk][3], qa_l[kk][3]);
        }
    }

    float o[8][4];
#pragma unroll
    for (int d = 0; d < 8; d++)
#pragma unroll
        for (int e = 0; e < 4; e++) o[d][e] = 0.f;
    float mrun0 = -1e30f, mrun1 = -1e30f, lrun0 = 0.f, lrun1 = 0.f;

    // cp.async prefetch of one chunk (4 planes x 64 rows x 128B payload)
    auto prefetch = [&](int kc, int s) {
        const uint32_t dstStage = smBase + (uint32_t)s * 4 * PLB;
#pragma unroll
        for (int t = 0; t < 8; t++) {
            const int plane = t >> 1;                      // compile-time after unroll
            const int inner = ((t & 1) << 8) + tid;        // 0..511
            const int r  = inner >> 3;
            const int c8 = inner & 7;
            const uint32_t dst = dstStage + (uint32_t)plane * PLB + r * (DPAD * 2) + c8 * 16;
            const __nv_bfloat16* src =
                (plane == 0 ? g_kh : plane == 1 ? g_kl : plane == 2 ? g_vh : g_vl)
                + bhoff + (size_t)(kc + r) * DK + c8 * 8;
            CP_ASYNC16(dst, src);
        }
        CP_COMMIT();
    };

    // ldmatrix address components
    const int kRow = ((lane >> 4) & 1) * 8 + (lane & 7);
    const int kColH = ((lane >> 3) & 1) * 8;
    const int vRow = ((lane >> 3) & 1) * 8 + (lane & 7);
    const int vColH = (lane >> 4) * 8;

    int s = 0;
    prefetch(0, 0);

    for (int kc = 0; kc < SEQ; kc += SC) {
        CP_WAIT0();
        __syncthreads();
        if (kc + SC < SEQ) prefetch(kc + SC, s ^ 1);

        const uint32_t stage = smBase + (uint32_t)s * 4 * PLB;
        const uint32_t smK  = stage;
        const uint32_t smKl = stage + PLB;
        const uint32_t smV  = stage + 2 * PLB;
        const uint32_t smVl = stage + 3 * PLB;

        // ---- S = Q K^T ----
        float sc[8][4];
#pragma unroll
        for (int j = 0; j < 8; j++)
#pragma unroll
            for (int e = 0; e < 4; e++) sc[j][e] = 0.f;

#pragma unroll
        for (int kk = 0; kk < 4; kk++) {
            uint32_t kbh[8][2], kbl[8][2];
#pragma unroll
            for (int p = 0; p < 4; p++) {
                uint32_t off = (uint32_t)(((p * 16 + kRow) * DPAD) + kk * 16 + kColH) * 2;
                LDSM4(kbh[2*p][0], kbh[2*p][1], kbh[2*p+1][0], kbh[2*p+1][1], smK + off);
                LDSM4(kbl[2*p][0], kbl[2*p][1], kbl[2*p+1][0], kbl[2*p+1][1], smKl + off);
            }
#pragma unroll
            for (int j = 0; j < 8; j++) {
                MMA16816(sc[j], qa_h[kk], kbh[j]);
                MMA16816(sc[j], qa_h[kk], kbl[j]);
                MMA16816(sc[j], qa_l[kk], kbh[j]);
            }
        }

        // ---- online softmax in c-frag layout ----
        float mx0 = -1e30f, mx1 = -1e30f;
#pragma unroll
        for (int j = 0; j < 8; j++) {
            mx0 = fmaxf(mx0, fmaxf(sc[j][0], sc[j][1]));
            mx1 = fmaxf(mx1, fmaxf(sc[j][2], sc[j][3]));
        }
        mx0 = fmaxf(mx0, __shfl_xor_sync(0xffffffff, mx0, 1));
        mx0 = fmaxf(mx0, __shfl_xor_sync(0xffffffff, mx0, 2));
        mx1 = fmaxf(mx1, __shfl_xor_sync(0xffffffff, mx1, 1));
        mx1 = fmaxf(mx1, __shfl_xor_sync(0xffffffff, mx1, 2));

        const float nm0 = fmaxf(mrun0, mx0);
        const float nm1 = fmaxf(mrun1, mx1);
        const float corr0 = __expf(mrun0 - nm0);
        const float corr1 = __expf(mrun1 - nm1);
        mrun0 = nm0; mrun1 = nm1;

        float sum0 = 0.f, sum1 = 0.f;
#pragma unroll
        for (int j = 0; j < 8; j++) {
            sc[j][0] = __expf(sc[j][0] - nm0); sum0 += sc[j][0];
            sc[j][1] = __expf(sc[j][1] - nm0); sum0 += sc[j][1];
            sc[j][2] = __expf(sc[j][2] - nm1); sum1 += sc[j][2];
            sc[j][3] = __expf(sc[j][3] - nm1); sum1 += sc[j][3];
        }
        sum0 += __shfl_xor_sync(0xffffffff, sum0, 1);
        sum0 += __shfl_xor_sync(0xffffffff, sum0, 2);
        sum1 += __shfl_xor_sync(0xffffffff, sum1, 1);
        sum1 += __shfl_xor_sync(0xffffffff, sum1, 2);
        lrun0 = lrun0 * corr0 + sum0;
        lrun1 = lrun1 * corr1 + sum1;

#pragma unroll
        for (int d = 0; d < 8; d++) {
            o[d][0] *= corr0; o[d][1] *= corr0;
            o[d][2] *= corr1; o[d][3] *= corr1;
        }

        // ---- pack P to bf16 hi/lo a-frags ----
        uint32_t pa_h[4][4], pa_l[4][4];
#pragma unroll
        for (int kk2 = 0; kk2 < 4; kk2++) {
            const int jL = 2 * kk2, jH = 2 * kk2 + 1;
            pk2split(sc[jL][0], sc[jL][1], pa_h[kk2][0], pa_l[kk2][0]);
            pk2split(sc[jL][2], sc[jL][3], pa_h[kk2][1], pa_l[kk2][1]);
            pk2split(sc[jH][0], sc[jH][1], pa_h[kk2][2], pa_l[kk2][2]);
            pk2split(sc[jH][2], sc[jH][3], pa_h[kk2][3], pa_l[kk2][3]);
        }

        // ---- O += P V ----
#pragma unroll
        for (int kk2 = 0; kk2 < 4; kk2++) {
            uint32_t vbh[8][2], vbl[8][2];
#pragma unroll
            for (int e = 0; e < 4; e++) {
                uint32_t off = (uint32_t)(((kk2 * 16 + vRow) * DPAD) + e * 16 + vColH) * 2;
                LDSM4T(vbh[2*e][0], vbh[2*e][1], vbh[2*e+1][0], vbh[2*e+1][1], smV + off);
                LDSM4T(vbl[2*e][0], vbl[2*e][1], vbl[2*e+1][0], vbl[2*e+1][1], smVl + off);
            }
#pragma unroll
            for (int d = 0; d < 8; d++) {
                MMA16816(o[d], pa_h[kk2], vbh[d]);
                MMA16816(o[d], pa_h[kk2], vbl[d]);
                MMA16816(o[d], pa_l[kk2], vbh[d]);
            }
        }
        s ^= 1;
    }

    // ---- epilogue ----
    const float inv0 = 1.f / lrun0;
    const float inv1 = 1.f / lrun1;
    float* c0 = g_ctx + ((size_t)(b * SEQ) + qrow0 + g) * HID + h * DK;
    float* c8 = c0 + 8 * HID;
#pragma unroll
    for (int d = 0; d < 8; d++) {
        float2 v;
        v.x = o[d][0] * inv0; v.y = o[d][1] * inv0;
        *(float2*)(c0 + d * 8 + 2 * tg) = v;
        v.x = o[d][2] * inv1; v.y = o[d][3] * inv1;
        *(float2*)(c8 + d * 8 + 2 * tg) = v;
    }
}

// ---------------------------------------------------------------------------
extern "C" void kernel_launch(void* const* d_in, const int* in_sizes, int n_in,
                              void* d_out, int out_size)
{
    (void)in_sizes; (void)n_in; (void)out_size;
    const float* tgt = (const float*)d_in[0];
    const float* Wq  = (const float*)d_in[1];
    const float* bq  = (const float*)d_in[2];
    const float* Wk  = (const float*)d_in[3];
    const float* bk  = (const float*)d_in[4];
    const float* Wv  = (const float*)d_in[5];
    const float* bv  = (const float*)d_in[6];
    const float* Wo  = (const float*)d_in[7];
    const float* bo  = (const float*)d_in[8];
    float* out = (float*)d_out;

    cudaFuncSetAttribute(gemm_mma<0>, cudaFuncAttributeMaxDynamicSharedMemorySize, GEMM_SMEM);
    cudaFuncSetAttribute(gemm_mma<1>, cudaFuncAttributeMaxDynamicSharedMemorySize, GEMM_SMEM);
    cudaFuncSetAttribute(attn_mma,    cudaFuncAttributeMaxDynamicSharedMemorySize, ATTN_SMEM);

    dim3 gQKV(MTOT / 128, HID / 128, 3);
    gemm_mma<0><<<gQKV, 256, GEMM_SMEM>>>(tgt, Wq, bq, Wk, bk, Wv, bv, nullptr);

    dim3 gATT(SEQ / QB, NH, BATCH);
    attn_mma<<<gATT, 256, ATTN_SMEM>>>();

    dim3 gOUT(MTOT / 128, HID / 128, 1);
    gemm_mma<1><<<gOUT, 256, GEMM_SMEM>>>(nullptr, Wo, bo, nullptr, nullptr, nullptr, nullptr, out);
}

// round 10
// speedup vs baseline: 1.1708x; 1.1708x over previous
#include <cuda_runtime.h>
#include <cuda_bf16.h>
#include <cstdint>

#define HID   1024
#define NH    16
#define DK    64
#define BATCH 4
#define SEQ   2048
#define MTOT  (BATCH*SEQ)

// ---- mma.sync / ldmatrix / cp.async helpers (base compute_100 features) ----
__device__ __forceinline__ uint32_t smem_to_u32(const void* p) {
    uint32_t a;
    asm("{ .reg .u64 t; cvta.to.shared.u64 t, %1; cvt.u32.u64 %0, t; }" : "=r"(a) : "l"(p));
    return a;
}
#define LDSM4(r0, r1, r2, r3, addr) \
    asm volatile("ldmatrix.sync.aligned.m8n8.x4.shared.b16 {%0,%1,%2,%3},[%4];" \
        : "=r"(r0), "=r"(r1), "=r"(r2), "=r"(r3) : "r"(addr))
#define LDSM4T(r0, r1, r2, r3, addr) \
    asm volatile("ldmatrix.sync.aligned.m8n8.x4.trans.shared.b16 {%0,%1,%2,%3},[%4];" \
        : "=r"(r0), "=r"(r1), "=r"(r2), "=r"(r3) : "r"(addr))
#define MMA16816(c, a, b) \
    asm volatile("mma.sync.aligned.m16n8k16.row.col.f32.bf16.bf16.f32 " \
        "{%0,%1,%2,%3},{%4,%5,%6,%7},{%8,%9},{%0,%1,%2,%3};" \
        : "+f"((c)[0]), "+f"((c)[1]), "+f"((c)[2]), "+f"((c)[3]) \
        : "r"((a)[0]), "r"((a)[1]), "r"((a)[2]), "r"((a)[3]), "r"((b)[0]), "r"((b)[1]))
#define CP_ASYNC16(dst, src) \
    asm volatile("cp.async.ca.shared.global [%0], [%1], 16;" :: "r"(dst), "l"(src) : "memory")
#define CP_COMMIT()  asm volatile("cp.async.commit_group;" ::: "memory")
#define CP_WAIT0()   asm volatile("cp.async.wait_group 0;" ::: "memory")

// bf16 2-term split helpers
__device__ __forceinline__ void bf16split(float x, __nv_bfloat16& h, __nv_bfloat16& l) {
    h = __float2bfloat16_rn(x);
    l = __float2bfloat16_rn(x - __bfloat162float(h));
}
__device__ __forceinline__ uint32_t pkbf(__nv_bfloat16 a, __nv_bfloat16 b) {
    __nv_bfloat162 t(a, b);
    return *(uint32_t*)&t;
}
__device__ __forceinline__ void pk2split(float x, float y, uint32_t& h, uint32_t& l) {
    __nv_bfloat16 hx, lx, hy, ly;
    bf16split(x, hx, lx); bf16split(y, hy, ly);
    h = pkbf(hx, hy); l = pkbf(lx, ly);
}

// Scratch (allocation-free rule: __device__ globals)
__device__ float g_q[(size_t)BATCH*NH*SEQ*DK];           // fp32, pre-scaled by 1/8
__device__ __nv_bfloat16 g_kh[(size_t)BATCH*NH*SEQ*DK];  // pre-split K hi plane
__device__ __nv_bfloat16 g_kl[(size_t)BATCH*NH*SEQ*DK];  // K lo plane
__device__ __nv_bfloat16 g_vh[(size_t)BATCH*NH*SEQ*DK];
__device__ __nv_bfloat16 g_vl[(size_t)BATCH*NH*SEQ*DK];
__device__ float g_ctx[(size_t)MTOT*HID];

// ---------------------------------------------------------------------------
// bf16-split tensor-core GEMM: Y = X W^T + bias
// Staging = exact R6-measured pattern (two threads per row, bf16x2 stores).
// MODE 0, z=0: -> g_q (fp32, scaled); z=1: -> g_kh/g_kl; z=2: -> g_vh/g_vl
// MODE 1: g_ctx -> OutPlain
// ---------------------------------------------------------------------------
#define BK      32
#define NKT     (HID / BK)
#define KPAD    40
#define PLANE   (128 * KPAD)
#define STG     (4 * PLANE)
#define GEMM_SMEM (2 * STG * 2)

template<int MODE>
__global__ __launch_bounds__(256)
void gemm_mma(const float* __restrict__ Xin,
              const float* __restrict__ W0, const float* __restrict__ B0,
              const float* __restrict__ W1, const float* __restrict__ B1,
              const float* __restrict__ W2, const float* __restrict__ B2,
              float* __restrict__ OutPlain)
{
    extern __shared__ __nv_bfloat16 sm[];
    const uint32_t smb = smem_to_u32(sm);

    const float* X = (MODE == 1) ? g_ctx : Xin;
    const int z = blockIdx.z;
    const float* W;
    const float* bias;
    if (MODE == 0) {
        W    = (z == 0) ? W0 : ((z == 1) ? W1 : W2);
        bias = (z == 0) ? B0 : ((z == 1) ? B1 : B2);
    } else {
        W = W0; bias = B0;
    }

    const int m0   = blockIdx.x * 128;
    const int n0   = blockIdx.y * 128;
    const int tid  = threadIdx.x;
    const int wid  = tid >> 5;
    const int lane = tid & 31;
    const int warp_m = (wid >> 2) * 64;
    const int warp_n = (wid & 3) * 32;

    // R6-measured staging: each thread handles one A half-row + one B half-row
    const int rowL = tid >> 1;
    const int colf = (tid & 1) << 4;
    const float* aSrc = X + (size_t)(m0 + rowL) * HID + colf;
    const float* bSrc = W + (size_t)(n0 + rowL) * HID + colf;

    float4 ra[4], rb[4];
    auto G2R = [&](int kt) {
        const float* a = aSrc + kt * BK;
        const float* b = bSrc + kt * BK;
#pragma unroll
        for (int i = 0; i < 4; i++) {
            ra[i] = *(const float4*)(a + i * 4);
            rb[i] = *(const float4*)(b + i * 4);
        }
    };
    auto R2S = [&](int s) {
        __nv_bfloat162* Ah = (__nv_bfloat162*)(sm + s * STG + 0 * PLANE + rowL * KPAD + colf);
        __nv_bfloat162* Al = (__nv_bfloat162*)(sm + s * STG + 1 * PLANE + rowL * KPAD + colf);
        __nv_bfloat162* Bh = (__nv_bfloat162*)(sm + s * STG + 2 * PLANE + rowL * KPAD + colf);
        __nv_bfloat162* Bl = (__nv_bfloat162*)(sm + s * STG + 3 * PLANE + rowL * KPAD + colf);
#pragma unroll
        for (int i = 0; i < 4; i++) {
            __nv_bfloat16 hx, lx, hy, ly, hz, lz, hw, lw;
            bf16split(ra[i].x, hx, lx); bf16split(ra[i].y, hy, ly);
            bf16split(ra[i].z, hz, lz); bf16split(ra[i].w, hw, lw);
            Ah[i*2] = __nv_bfloat162(hx, hy); Ah[i*2+1] = __nv_bfloat162(hz, hw);
            Al[i*2] = __nv_bfloat162(lx, ly); Al[i*2+1] = __nv_bfloat162(lz, lw);
            bf16split(rb[i].x, hx, lx); bf16split(rb[i].y, hy, ly);
            bf16split(rb[i].z, hz, lz); bf16split(rb[i].w, hw, lw);
            Bh[i*2] = __nv_bfloat162(hx, hy); Bh[i*2+1] = __nv_bfloat162(hz, hw);
            Bl[i*2] = __nv_bfloat162(lx, ly); Bl[i*2+1] = __nv_bfloat162(lz, lw);
        }
    };

    float acc[4][4][4];
#pragma unroll
    for (int mt = 0; mt < 4; mt++)
#pragma unroll
        for (int nt = 0; nt < 4; nt++)
#pragma unroll
            for (int e = 0; e < 4; e++) acc[mt][nt][e] = 0.f;

    const int arow = warp_m + (lane & 15);
    const int acolL = (lane >> 4) * 8;
    const int brow = warp_n + ((lane >> 4) & 1) * 8 + (lane & 7);
    const int bcolL = ((lane >> 3) & 1) * 8;

    G2R(0); R2S(0);
    __syncthreads();

    for (int kt = 0; kt < NKT; kt++) {
        const int s = kt & 1;
        if (kt + 1 < NKT) G2R(kt + 1);

        const uint32_t sb = smb + (uint32_t)(s * STG) * 2;
        uint32_t ahi[4][4], alo[4][4], bhi[4][2], blo[4][2];
#pragma unroll
        for (int sub = 0; sub < 2; sub++) {
            const int kks = sub * 16;
#pragma unroll
            for (int mt = 0; mt < 4; mt++) {
                uint32_t ad = sb + (uint32_t)(((arow + mt * 16) * KPAD) + kks + acolL) * 2;
                LDSM4(ahi[mt][0], ahi[mt][1], ahi[mt][2], ahi[mt][3], ad);
                LDSM4(alo[mt][0], alo[mt][1], alo[mt][2], alo[mt][3], ad + PLANE * 2);
            }
#pragma unroll
            for (int p = 0; p < 2; p++) {
                uint32_t bd = sb + (uint32_t)(2 * PLANE + ((brow + p * 16) * KPAD) + kks + bcolL) * 2;
                LDSM4(bhi[2*p][0], bhi[2*p][1], bhi[2*p+1][0], bhi[2*p+1][1], bd);
                LDSM4(blo[2*p][0], blo[2*p][1], blo[2*p+1][0], blo[2*p+1][1], bd + PLANE * 2);
            }
#pragma unroll
            for (int mt = 0; mt < 4; mt++)
#pragma unroll
                for (int nt = 0; nt < 4; nt++) {
                    MMA16816(acc[mt][nt], ahi[mt], bhi[nt]);
                    MMA16816(acc[mt][nt], ahi[mt], blo[nt]);
                    MMA16816(acc[mt][nt], alo[mt], bhi[nt]);
                }
        }

        if (kt + 1 < NKT) R2S((kt + 1) & 1);
        __syncthreads();
    }

    const int g  = lane >> 2;
    const int tg = lane & 3;
#pragma unroll
    for (int mt = 0; mt < 4; mt++) {
        const int m1 = m0 + warp_m + mt * 16 + g;
        const int m2 = m1 + 8;
#pragma unroll
        for (int nt = 0; nt < 4; nt++) {
            const int n = n0 + warp_n + nt * 8 + tg * 2;
            const float bv0 = __ldg(bias + n);
            const float bv1 = __ldg(bias + n + 1);
            const float* c = acc[mt][nt];
            if (MODE == 0) {
                const int hh = n >> 6, d = n & 63;
                const size_t i1 = (((size_t)((m1 >> 11) * NH + hh)) * SEQ + (m1 & 2047)) * DK + d;
                const size_t i2 = (((size_t)((m2 >> 11) * NH + hh)) * SEQ + (m2 & 2047)) * DK + d;
                const float v0 = c[0] + bv0, v1 = c[1] + bv1;
                const float v2 = c[2] + bv0, v3 = c[3] + bv1;
                if (z == 0) {
                    *(float2*)(g_q + i1) = make_float2(v0 * 0.125f, v1 * 0.125f);
                    *(float2*)(g_q + i2) = make_float2(v2 * 0.125f, v3 * 0.125f);
                } else {
                    __nv_bfloat16* ph = (z == 1) ? g_kh : g_vh;
                    __nv_bfloat16* pl = (z == 1) ? g_kl : g_vl;
                    __nv_bfloat16 h0, l0, h1, l1;
                    bf16split(v0, h0, l0); bf16split(v1, h1, l1);
                    *(__nv_bfloat162*)(ph + i1) = __nv_bfloat162(h0, h1);
                    *(__nv_bfloat162*)(pl + i1) = __nv_bfloat162(l0, l1);
                    bf16split(v2, h0, l0); bf16split(v3, h1, l1);
                    *(__nv_bfloat162*)(ph + i2) = __nv_bfloat162(h0, h1);
                    *(__nv_bfloat162*)(pl + i2) = __nv_bfloat162(l0, l1);
                }
            } else {
                *(float2*)(OutPlain + (size_t)m1 * HID + n) = make_float2(c[0] + bv0, c[1] + bv1);
                *(float2*)(OutPlain + (size_t)m2 * HID + n) = make_float2(c[2] + bv0, c[3] + bv1);
            }
        }
    }
}

// ---------------------------------------------------------------------------
// Flash attention on tensor cores. K/V pre-split bf16 hi/lo in gmem;
// staged via double-buffered cp.async (no conversion in the loop).
// CTA: 128 queries, 8 warps (16 rows each). Key chunks of 64.
// ---------------------------------------------------------------------------
#define SC    64
#define QB    128
#define DPAD  72                   // 144B rows: conflict-free ldmatrix + 16B aligned
#define PLB   (SC * DPAD * 2)      // plane bytes = 9216
#define ATTN_SMEM (2 * 4 * PLB)    // 2 stages x 4 planes = 73728

__global__ __launch_bounds__(256)
void attn_mma()
{
    extern __shared__ __nv_bfloat16 asmem[];
    const uint32_t smBase = smem_to_u32(asmem);

    const int b    = blockIdx.z;
    const int h    = blockIdx.y;
    const int tid  = threadIdx.x;
    const int wid  = tid >> 5;
    const int lane = tid & 31;
    const int g    = lane >> 2;
    const int tg   = lane & 3;

    const size_t bh = (size_t)(b * NH + h);
    const size_t bhoff = bh * SEQ * DK;
    const int qrow0 = blockIdx.x * QB + wid * 16;

    // ---- Q a-frags (hi/lo) from fp32 gmem, loaded once ----
    uint32_t qa_h[4][4], qa_l[4][4];
    {
        const float* q0 = g_q + (bh * SEQ + qrow0 + g) * DK;
        const float* q8 = q0 + 8 * DK;
#pragma unroll
        for (int kk = 0; kk < 4; kk++) {
            float2 v;
            v = *(const float2*)(q0 + kk * 16 + 2 * tg);
            pk2split(v.x, v.y, qa_h[kk][0], qa_l[kk][0]);
            v = *(const float2*)(q8 + kk * 16 + 2 * tg);
            pk2split(v.x, v.y, qa_h[kk][1], qa_l[kk][1]);
            v = *(const float2*)(q0 + kk * 16 + 8 + 2 * tg);
            pk2split(v.x, v.y, qa_h[kk][2], qa_l[kk][2]);
            v = *(const float2*)(q8 + kk * 16 + 8 + 2 * tg);
            pk2split(v.x, v.y, qa_h[kk][3], qa_l[kk][3]);
        }
    }

    float o[8][4];
#pragma unroll
    for (int d = 0; d < 8; d++)
#pragma unroll
        for (int e = 0; e < 4; e++) o[d][e] = 0.f;
    float mrun0 = -1e30f, mrun1 = -1e30f, lrun0 = 0.f, lrun1 = 0.f;

    // cp.async prefetch of one chunk (4 planes x 64 rows x 128B payload)
    auto prefetch = [&](int kc, int s) {
        const uint32_t dstStage = smBase + (uint32_t)s * 4 * PLB;
#pragma unroll
        for (int t = 0; t < 8; t++) {
            const int plane = t >> 1;
            const int inner = ((t & 1) << 8) + tid;
            const int r  = inner >> 3;
            const int c8 = inner & 7;
            const uint32_t dst = dstStage + (uint32_t)plane * PLB + r * (DPAD * 2) + c8 * 16;
            const __nv_bfloat16* src =
                (plane == 0 ? g_kh : plane == 1 ? g_kl : plane == 2 ? g_vh : g_vl)
                + bhoff + (size_t)(kc + r) * DK + c8 * 8;
            CP_ASYNC16(dst, src);
        }
        CP_COMMIT();
    };

    // ldmatrix address components
    const int kRow = ((lane >> 4) & 1) * 8 + (lane & 7);
    const int kColH = ((lane >> 3) & 1) * 8;
    const int vRow = ((lane >> 3) & 1) * 8 + (lane & 7);
    const int vColH = (lane >> 4) * 8;

    int s = 0;
    prefetch(0, 0);

    for (int kc = 0; kc < SEQ; kc += SC) {
        CP_WAIT0();
        __syncthreads();
        if (kc + SC < SEQ) prefetch(kc + SC, s ^ 1);

        const uint32_t stage = smBase + (uint32_t)s * 4 * PLB;
        const uint32_t smK  = stage;
        const uint32_t smKl = stage + PLB;
        const uint32_t smV  = stage + 2 * PLB;
        const uint32_t smVl = stage + 3 * PLB;

        // ---- S = Q K^T ----
        float sc[8][4];
#pragma unroll
        for (int j = 0; j < 8; j++)
#pragma unroll
            for (int e = 0; e < 4; e++) sc[j][e] = 0.f;

#pragma unroll
        for (int kk = 0; kk < 4; kk++) {
            uint32_t kbh[8][2], kbl[8][2];
#pragma unroll
            for (int p = 0; p < 4; p++) {
                uint32_t off = (uint32_t)(((p * 16 + kRow) * DPAD) + kk * 16 + kColH) * 2;
                LDSM4(kbh[2*p][0], kbh[2*p][1], kbh[2*p+1][0], kbh[2*p+1][1], smK + off);
                LDSM4(kbl[2*p][0], kbl[2*p][1], kbl[2*p+1][0], kbl[2*p+1][1], smKl + off);
            }
#pragma unroll
            for (int j = 0; j < 8; j++) {
                MMA16816(sc[j], qa_h[kk], kbh[j]);
                MMA16816(sc[j], qa_h[kk], kbl[j]);
                MMA16816(sc[j], qa_l[kk], kbh[j]);
            }
        }

        // ---- online softmax in c-frag layout ----
        float mx0 = -1e30f, mx1 = -1e30f;
#pragma unroll
        for (int j = 0; j < 8; j++) {
            mx0 = fmaxf(mx0, fmaxf(sc[j][0], sc[j][1]));
            mx1 = fmaxf(mx1, fmaxf(sc[j][2], sc[j][3]));
        }
        mx0 = fmaxf(mx0, __shfl_xor_sync(0xffffffff, mx0, 1));
        mx0 = fmaxf(mx0, __shfl_xor_sync(0xffffffff, mx0, 2));
        mx1 = fmaxf(mx1, __shfl_xor_sync(0xffffffff, mx1, 1));
        mx1 = fmaxf(mx1, __shfl_xor_sync(0xffffffff, mx1, 2));

        const float nm0 = fmaxf(mrun0, mx0);
        const float nm1 = fmaxf(mrun1, mx1);
        const float corr0 = __expf(mrun0 - nm0);
        const float corr1 = __expf(mrun1 - nm1);
        mrun0 = nm0; mrun1 = nm1;

        float sum0 = 0.f, sum1 = 0.f;
#pragma unroll
        for (int j = 0; j < 8; j++) {
            sc[j][0] = __expf(sc[j][0] - nm0); sum0 += sc[j][0];
            sc[j][1] = __expf(sc[j][1] - nm0); sum0 += sc[j][1];
            sc[j][2] = __expf(sc[j][2] - nm1); sum1 += sc[j][2];
            sc[j][3] = __expf(sc[j][3] - nm1); sum1 += sc[j][3];
        }
        sum0 += __shfl_xor_sync(0xffffffff, sum0, 1);
        sum0 += __shfl_xor_sync(0xffffffff, sum0, 2);
        sum1 += __shfl_xor_sync(0xffffffff, sum1, 1);
        sum1 += __shfl_xor_sync(0xffffffff, sum1, 2);
        lrun0 = lrun0 * corr0 + sum0;
        lrun1 = lrun1 * corr1 + sum1;

#pragma unroll
        for (int d = 0; d < 8; d++) {
            o[d][0] *= corr0; o[d][1] *= corr0;
            o[d][2] *= corr1; o[d][3] *= corr1;
        }

        // ---- pack P to bf16 hi/lo a-frags ----
        uint32_t pa_h[4][4], pa_l[4][4];
#pragma unroll
        for (int kk2 = 0; kk2 < 4; kk2++) {
            const int jL = 2 * kk2, jH = 2 * kk2 + 1;
            pk2split(sc[jL][0], sc[jL][1], pa_h[kk2][0], pa_l[kk2][0]);
            pk2split(sc[jL][2], sc[jL][3], pa_h[kk2][1], pa_l[kk2][1]);
            pk2split(sc[jH][0], sc[jH][1], pa_h[kk2][2], pa_l[kk2][2]);
            pk2split(sc[jH][2], sc[jH][3], pa_h[kk2][3], pa_l[kk2][3]);
        }

        // ---- O += P V ----
#pragma unroll
        for (int kk2 = 0; kk2 < 4; kk2++) {
            uint32_t vbh[8][2], vbl[8][2];
#pragma unroll
            for (int e = 0; e < 4; e++) {
                uint32_t off = (uint32_t)(((kk2 * 16 + vRow) * DPAD) + e * 16 + vColH) * 2;
                LDSM4T(vbh[2*e][0], vbh[2*e][1], vbh[2*e+1][0], vbh[2*e+1][1], smV + off);
                LDSM4T(vbl[2*e][0], vbl[2*e][1], vbl[2*e+1][0], vbl[2*e+1][1], smVl + off);
            }
#pragma unroll
            for (int d = 0; d < 8; d++) {
                MMA16816(o[d], pa_h[kk2], vbh[d]);
                MMA16816(o[d], pa_h[kk2], vbl[d]);
                MMA16816(o[d], pa_l[kk2], vbh[d]);
            }
        }
        s ^= 1;
    }

    // ---- epilogue ----
    const float inv0 = 1.f / lrun0;
    const float inv1 = 1.f / lrun1;
    float* c0 = g_ctx + ((size_t)(b * SEQ) + qrow0 + g) * HID + h * DK;
    float* c8 = c0 + 8 * HID;
#pragma unroll
    for (int d = 0; d < 8; d++) {
        float2 v;
        v.x = o[d][0] * inv0; v.y = o[d][1] * inv0;
        *(float2*)(c0 + d * 8 + 2 * tg) = v;
        v.x = o[d][2] * inv1; v.y = o[d][3] * inv1;
        *(float2*)(c8 + d * 8 + 2 * tg) = v;
    }
}

// ---------------------------------------------------------------------------
extern "C" void kernel_launch(void* const* d_in, const int* in_sizes, int n_in,
                              void* d_out, int out_size)
{
    (void)in_sizes; (void)n_in; (void)out_size;
    const float* tgt = (const float*)d_in[0];
    const float* Wq  = (const float*)d_in[1];
    const float* bq  = (const float*)d_in[2];
    const float* Wk  = (const float*)d_in[3];
    const float* bk  = (const float*)d_in[4];
    const float* Wv  = (const float*)d_in[5];
    const float* bv  = (const float*)d_in[6];
    const float* Wo  = (const float*)d_in[7];
    const float* bo  = (const float*)d_in[8];
    float* out = (float*)d_out;

    cudaFuncSetAttribute(gemm_mma<0>, cudaFuncAttributeMaxDynamicSharedMemorySize, GEMM_SMEM);
    cudaFuncSetAttribute(gemm_mma<1>, cudaFuncAttributeMaxDynamicSharedMemorySize, GEMM_SMEM);
    cudaFuncSetAttribute(attn_mma,    cudaFuncAttributeMaxDynamicSharedMemorySize, ATTN_SMEM);

    dim3 gQKV(MTOT / 128, HID / 128, 3);
    gemm_mma<0><<<gQKV, 256, GEMM_SMEM>>>(tgt, Wq, bq, Wk, bk, Wv, bv, nullptr);

    dim3 gATT(SEQ / QB, NH, BATCH);
    attn_mma<<<gATT, 256, ATTN_SMEM>>>();

    dim3 gOUT(MTOT / 128, HID / 128, 1);
    gemm_mma<1><<<gOUT, 256, GEMM_SMEM>>>(nullptr, Wo, bo, nullptr, nullptr, nullptr, nullptr, out);
}

// round 14
// speedup vs baseline: 1.2216x; 1.0434x over previous
#include <cuda_runtime.h>
#include <cuda_bf16.h>
#include <cstdint>

#define HID   1024
#define NH    16
#define DK    64
#define BATCH 4
#define SEQ   2048
#define MTOT  (BATCH*SEQ)

// ---- mma.sync / ldmatrix / cp.async helpers ----
__device__ __forceinline__ uint32_t smem_to_u32(const void* p) {
    uint32_t a;
    asm("{ .reg .u64 t; cvta.to.shared.u64 t, %1; cvt.u32.u64 %0, t; }" : "=r"(a) : "l"(p));
    return a;
}
#define LDSM4(r0, r1, r2, r3, addr) \
    asm volatile("ldmatrix.sync.aligned.m8n8.x4.shared.b16 {%0,%1,%2,%3},[%4];" \
        : "=r"(r0), "=r"(r1), "=r"(r2), "=r"(r3) : "r"(addr))
#define LDSM4T(r0, r1, r2, r3, addr) \
    asm volatile("ldmatrix.sync.aligned.m8n8.x4.trans.shared.b16 {%0,%1,%2,%3},[%4];" \
        : "=r"(r0), "=r"(r1), "=r"(r2), "=r"(r3) : "r"(addr))
#define MMA16816(c, a, b) \
    asm volatile("mma.sync.aligned.m16n8k16.row.col.f32.bf16.bf16.f32 " \
        "{%0,%1,%2,%3},{%4,%5,%6,%7},{%8,%9},{%0,%1,%2,%3};" \
        : "+f"((c)[0]), "+f"((c)[1]), "+f"((c)[2]), "+f"((c)[3]) \
        : "r"((a)[0]), "r"((a)[1]), "r"((a)[2]), "r"((a)[3]), "r"((b)[0]), "r"((b)[1]))
#define CP_ASYNC16(dst, src) \
    asm volatile("cp.async.ca.shared.global [%0], [%1], 16;" :: "r"(dst), "l"(src) : "memory")
#define CP_COMMIT()  asm volatile("cp.async.commit_group;" ::: "memory")
#define CP_WAIT0()   asm volatile("cp.async.wait_group 0;" ::: "memory")
#define CP_WAIT1()   asm volatile("cp.async.wait_group 1;" ::: "memory")

// bf16 2-term split helpers
__device__ __forceinline__ void bf16split(float x, __nv_bfloat16& h, __nv_bfloat16& l) {
    h = __float2bfloat16_rn(x);
    l = __float2bfloat16_rn(x - __bfloat162float(h));
}
__device__ __forceinline__ uint32_t pkbf(__nv_bfloat16 a, __nv_bfloat16 b) {
    __nv_bfloat162 t(a, b);
    return *(uint32_t*)&t;
}
__device__ __forceinline__ void pk2split_c(float x, float y, uint32_t& h, uint32_t& l) {
    __nv_bfloat16 hx, lx, hy, ly;
    bf16split(x, hx, lx); bf16split(y, hy, ly);
    h = pkbf(hx, hy); l = pkbf(lx, ly);
}

// Scratch (allocation-free rule: __device__ globals)
__device__ float g_q[(size_t)BATCH*NH*SEQ*DK];           // fp32, pre-scaled by 1/8
__device__ __nv_bfloat16 g_kh[(size_t)BATCH*NH*SEQ*DK];
__device__ __nv_bfloat16 g_kl[(size_t)BATCH*NH*SEQ*DK];
__device__ __nv_bfloat16 g_vh[(size_t)BATCH*NH*SEQ*DK];
__device__ __nv_bfloat16 g_vl[(size_t)BATCH*NH*SEQ*DK];
// pre-split operand planes
__device__ __nv_bfloat16 g_xh[(size_t)MTOT*HID], g_xl[(size_t)MTOT*HID];    // tgt
__device__ __nv_bfloat16 g_ch[(size_t)MTOT*HID], g_cl[(size_t)MTOT*HID];    // ctx
__device__ __nv_bfloat16 g_wqh[(size_t)HID*HID], g_wql[(size_t)HID*HID];
__device__ __nv_bfloat16 g_wkh[(size_t)HID*HID], g_wkl[(size_t)HID*HID];
__device__ __nv_bfloat16 g_wvh[(size_t)HID*HID], g_wvl[(size_t)HID*HID];
__device__ __nv_bfloat16 g_woh[(size_t)HID*HID], g_wol[(size_t)HID*HID];

// ---------------------------------------------------------------------------
// Pre-pass: fp32 -> bf16 hi/lo planes. Destination selected by template
// (device-side symbol references — no cudaGetSymbolAddress needed).
// WHICH: 0=tgt->xh/xl, 1=Wq, 2=Wk, 3=Wv, 4=Wo
// ---------------------------------------------------------------------------
template<int WHICH>
__global__ void split_pre(const float* __restrict__ src, int n4)
{
    __nv_bfloat16* dh;
    __nv_bfloat16* dl;
    if      (WHICH == 0) { dh = g_xh;  dl = g_xl;  }
    else if (WHICH == 1) { dh = g_wqh; dl = g_wql; }
    else if (WHICH == 2) { dh = g_wkh; dl = g_wkl; }
    else if (WHICH == 3) { dh = g_wvh; dl = g_wvl; }
    else                 { dh = g_woh; dl = g_wol; }

    int i = blockIdx.x * blockDim.x + threadIdx.x;
    if (i >= n4) return;
    float4 v = ((const float4*)src)[i];
    __nv_bfloat16 h0, l0, h1, l1, h2, l2, h3, l3;
    bf16split(v.x, h0, l0); bf16split(v.y, h1, l1);
    bf16split(v.z, h2, l2); bf16split(v.w, h3, l3);
    uint2 hv, lv;
    hv.x = pkbf(h0, h1); hv.y = pkbf(h2, h3);
    lv.x = pkbf(l0, l1); lv.y = pkbf(l2, l3);
    ((uint2*)dh)[i] = hv;
    ((uint2*)dl)[i] = lv;
}

// ---------------------------------------------------------------------------
// bf16-split tensor-core GEMM, cp.async staging from pre-split planes.
// 3-stage pipeline. Y = X W^T + bias.
// MODE 0: X=g_xh/l, W per z -> g_q (scaled) / g_kh,kl / g_vh,vl
// MODE 1: X=g_ch/l, W=g_woh/l -> OutPlain
// ---------------------------------------------------------------------------
#define BK      32
#define NKT     (HID / BK)
#define KPAD    40
#define PLANE   (128 * KPAD)       // elements per plane per stage
#define PLANEB  (PLANE * 2)        // bytes = 10240
#define STGB    (4 * PLANEB)       // bytes per stage = 40960
#define GEMM_SMEM (3 * STGB)       // 122880

template<int MODE>
__global__ __launch_bounds__(256)
void gemm_mma(const float* __restrict__ Bq,
              const float* __restrict__ Bk,
              const float* __restrict__ Bv,
              float* __restrict__ OutPlain)
{
    extern __shared__ __nv_bfloat16 sm[];
    const uint32_t smb = smem_to_u32(sm);

    const int z = blockIdx.z;
    const __nv_bfloat16* pAh = (MODE == 0) ? g_xh : g_ch;
    const __nv_bfloat16* pAl = (MODE == 0) ? g_xl : g_cl;
    const __nv_bfloat16* pBh;
    const __nv_bfloat16* pBl;
    const float* bias;
    if (MODE == 0) {
        pBh  = (z == 0) ? g_wqh : ((z == 1) ? g_wkh : g_wvh);
        pBl  = (z == 0) ? g_wql : ((z == 1) ? g_wkl : g_wvl);
        bias = (z == 0) ? Bq : ((z == 1) ? Bk : Bv);
    } else {
        pBh = g_woh; pBl = g_wol; bias = Bq;
    }

    const int m0   = blockIdx.x * 128;
    const int n0   = blockIdx.y * 128;
    const int tid  = threadIdx.x;
    const int wid  = tid >> 5;
    const int lane = tid & 31;
    const int warp_m = (wid >> 2) * 64;
    const int warp_n = (wid & 3) * 32;

    // cp.async staging: 4 planes x 128 rows x 4 chunks(16B) = 2048 chunks, 8/thread
    auto prefetch = [&](int kt, int s) {
        const uint32_t dstStage = smb + (uint32_t)s * STGB;
#pragma unroll
        for (int t = 0; t < 8; t++) {
            const int plane = t >> 1;                 // 0=Ah 1=Al 2=Bh 3=Bl
            const int inner = ((t & 1) << 8) + tid;   // 0..511
            const int r = inner >> 2;                 // 0..127
            const int c = inner & 3;                  // 0..3
            const uint32_t dst = dstStage + (uint32_t)plane * PLANEB + r * (KPAD * 2) + c * 16;
            const __nv_bfloat16* src =
                (plane == 0 ? pAh + (size_t)(m0 + r) * HID :
                 plane == 1 ? pAl + (size_t)(m0 + r) * HID :
                 plane == 2 ? pBh + (size_t)(n0 + r) * HID :
                              pBl + (size_t)(n0 + r) * HID) + kt * BK + c * 8;
            CP_ASYNC16(dst, src);
        }
        CP_COMMIT();
    };

    float acc[4][4][4];
#pragma unroll
    for (int mt = 0; mt < 4; mt++)
#pragma unroll
        for (int nt = 0; nt < 4; nt++)
#pragma unroll
            for (int e = 0; e < 4; e++) acc[mt][nt][e] = 0.f;

    const int arow = warp_m + (lane & 15);
    const int acolL = (lane >> 4) * 8;
    const int brow = warp_n + ((lane >> 4) & 1) * 8 + (lane & 7);
    const int bcolL = ((lane >> 3) & 1) * 8;

    prefetch(0, 0);
    prefetch(1, 1);

    for (int kt = 0; kt < NKT; kt++) {
        CP_WAIT1();
        __syncthreads();
        if (kt + 2 < NKT) prefetch(kt + 2, (kt + 2) % 3);

        const uint32_t sb = smb + (uint32_t)((kt % 3) * STGB);
        uint32_t ahi[4][4], alo[4][4], bhi[4][2], blo[4][2];
#pragma unroll
        for (int sub = 0; sub < 2; sub++) {
            const int kks = sub * 16;
#pragma unroll
            for (int mt = 0; mt < 4; mt++) {
                uint32_t ad = sb + (uint32_t)(((arow + mt * 16) * KPAD) + kks + acolL) * 2;
                LDSM4(ahi[mt][0], ahi[mt][1], ahi[mt][2], ahi[mt][3], ad);
                LDSM4(alo[mt][0], alo[mt][1], alo[mt][2], alo[mt][3], ad + PLANEB);
            }
#pragma unroll
            for (int p = 0; p < 2; p++) {
                uint32_t bd = sb + (uint32_t)(2 * PLANEB) +
                              (uint32_t)(((brow + p * 16) * KPAD) + kks + bcolL) * 2;
                LDSM4(bhi[2*p][0], bhi[2*p][1], bhi[2*p+1][0], bhi[2*p+1][1], bd);
                LDSM4(blo[2*p][0], blo[2*p][1], blo[2*p+1][0], blo[2*p+1][1], bd + PLANEB);
            }
#pragma unroll
            for (int mt = 0; mt < 4; mt++)
#pragma unroll
                for (int nt = 0; nt < 4; nt++) {
                    MMA16816(acc[mt][nt], ahi[mt], bhi[nt]);
                    MMA16816(acc[mt][nt], ahi[mt], blo[nt]);
                    MMA16816(acc[mt][nt], alo[mt], bhi[nt]);
                }
        }
        __syncthreads();
    }

    const int g  = lane >> 2;
    const int tg = lane & 3;
#pragma unroll
    for (int mt = 0; mt < 4; mt++) {
        const int m1 = m0 + warp_m + mt * 16 + g;
        const int m2 = m1 + 8;
#pragma unroll
        for (int nt = 0; nt < 4; nt++) {
            const int n = n0 + warp_n + nt * 8 + tg * 2;
            const float bv0 = __ldg(bias + n);
            const float bv1 = __ldg(bias + n + 1);
            const float* c = acc[mt][nt];
            if (MODE == 0) {
                const int hh = n >> 6, d = n & 63;
                const size_t i1 = (((size_t)((m1 >> 11) * NH + hh)) * SEQ + (m1 & 2047)) * DK + d;
                const size_t i2 = (((size_t)((m2 >> 11) * NH + hh)) * SEQ + (m2 & 2047)) * DK + d;
                const float v0 = c[0] + bv0, v1 = c[1] + bv1;
                const float v2 = c[2] + bv0, v3 = c[3] + bv1;
                if (z == 0) {
                    *(float2*)(g_q + i1) = make_float2(v0 * 0.125f, v1 * 0.125f);
                    *(float2*)(g_q + i2) = make_float2(v2 * 0.125f, v3 * 0.125f);
                } else {
                    __nv_bfloat16* ph = (z == 1) ? g_kh : g_vh;
                    __nv_bfloat16* pl = (z == 1) ? g_kl : g_vl;
                    __nv_bfloat16 h0, l0, h1, l1;
                    bf16split(v0, h0, l0); bf16split(v1, h1, l1);
                    *(__nv_bfloat162*)(ph + i1) = __nv_bfloat162(h0, h1);
                    *(__nv_bfloat162*)(pl + i1) = __nv_bfloat162(l0, l1);
                    bf16split(v2, h0, l0); bf16split(v3, h1, l1);
                    *(__nv_bfloat162*)(ph + i2) = __nv_bfloat162(h0, h1);
                    *(__nv_bfloat162*)(pl + i2) = __nv_bfloat162(l0, l1);
                }
            } else {
                *(float2*)(OutPlain + (size_t)m1 * HID + n) = make_float2(c[0] + bv0, c[1] + bv1);
                *(float2*)(OutPlain + (size_t)m2 * HID + n) = make_float2(c[2] + bv0, c[3] + bv1);
            }
        }
    }
}

// ---------------------------------------------------------------------------
// Flash attention on tensor cores (validated R10). Epilogue writes pre-split
// ctx planes for the out-projection.
// ---------------------------------------------------------------------------
#define SC    64
#define QB    128
#define DPAD  72
#define PLB   (SC * DPAD * 2)
#define ATTN_SMEM (2 * 4 * PLB)

__global__ __launch_bounds__(256)
void attn_mma()
{
    extern __shared__ __nv_bfloat16 asmem[];
    const uint32_t smBase = smem_to_u32(asmem);

    const int b    = blockIdx.z;
    const int h    = blockIdx.y;
    const int tid  = threadIdx.x;
    const int wid  = tid >> 5;
    const int lane = tid & 31;
    const int g    = lane >> 2;
    const int tg   = lane & 3;

    const size_t bh = (size_t)(b * NH + h);
    const size_t bhoff = bh * SEQ * DK;
    const int qrow0 = blockIdx.x * QB + wid * 16;

    uint32_t qa_h[4][4], qa_l[4][4];
    {
        const float* q0 = g_q + (bh * SEQ + qrow0 + g) * DK;
        const float* q8 = q0 + 8 * DK;
#pragma unroll
        for (int kk = 0; kk < 4; kk++) {
            float2 v;
            v = *(const float2*)(q0 + kk * 16 + 2 * tg);
            pk2split_c(v.x, v.y, qa_h[kk][0], qa_l[kk][0]);
            v = *(const float2*)(q8 + kk * 16 + 2 * tg);
            pk2split_c(v.x, v.y, qa_h[kk][1], qa_l[kk][1]);
            v = *(const float2*)(q0 + kk * 16 + 8 + 2 * tg);
            pk2split_c(v.x, v.y, qa_h[kk][2], qa_l[kk][2]);
            v = *(const float2*)(q8 + kk * 16 + 8 + 2 * tg);
            pk2split_c(v.x, v.y, qa_h[kk][3], qa_l[kk][3]);
        }
    }

    float o[8][4];
#pragma unroll
    for (int d = 0; d < 8; d++)
#pragma unroll
        for (int e = 0; e < 4; e++) o[d][e] = 0.f;
    float mrun0 = -1e30f, mrun1 = -1e30f, lrun0 = 0.f, lrun1 = 0.f;

    auto prefetch = [&](int kc, int s) {
        const uint32_t dstStage = smBase + (uint32_t)s * 4 * PLB;
#pragma unroll
        for (int t = 0; t < 8; t++) {
            const int plane = t >> 1;
            const int inner = ((t & 1) << 8) + tid;
            const int r  = inner >> 3;
            const int c8 = inner & 7;
            const uint32_t dst = dstStage + (uint32_t)plane * PLB + r * (DPAD * 2) + c8 * 16;
            const __nv_bfloat16* src =
                (plane == 0 ? g_kh : plane == 1 ? g_kl : plane == 2 ? g_vh : g_vl)
                + bhoff + (size_t)(kc + r) * DK + c8 * 8;
            CP_ASYNC16(dst, src);
        }
        CP_COMMIT();
    };

    const int kRow = ((lane >> 4) & 1) * 8 + (lane & 7);
    const int kColH = ((lane >> 3) & 1) * 8;
    const int vRow = ((lane >> 3) & 1) * 8 + (lane & 7);
    const int vColH = (lane >> 4) * 8;

    int s = 0;
    prefetch(0, 0);

    for (int kc = 0; kc < SEQ; kc += SC) {
        CP_WAIT0();
        __syncthreads();
        if (kc + SC < SEQ) prefetch(kc + SC, s ^ 1);

        const uint32_t stage = smBase + (uint32_t)s * 4 * PLB;
        const uint32_t smK  = stage;
        const uint32_t smKl = stage + PLB;
        const uint32_t smV  = stage + 2 * PLB;
        const uint32_t smVl = stage + 3 * PLB;

        float sc[8][4];
#pragma unroll
        for (int j = 0; j < 8; j++)
#pragma unroll
            for (int e = 0; e < 4; e++) sc[j][e] = 0.f;

#pragma unroll
        for (int kk = 0; kk < 4; kk++) {
            uint32_t kbh[8][2], kbl[8][2];
#pragma unroll
            for (int p = 0; p < 4; p++) {
                uint32_t off = (uint32_t)(((p * 16 + kRow) * DPAD) + kk * 16 + kColH) * 2;
                LDSM4(kbh[2*p][0], kbh[2*p][1], kbh[2*p+1][0], kbh[2*p+1][1], smK + off);
                LDSM4(kbl[2*p][0], kbl[2*p][1], kbl[2*p+1][0], kbl[2*p+1][1], smKl + off);
            }
#pragma unroll
            for (int j = 0; j < 8; j++) {
                MMA16816(sc[j], qa_h[kk], kbh[j]);
                MMA16816(sc[j], qa_h[kk], kbl[j]);
                MMA16816(sc[j], qa_l[kk], kbh[j]);
            }
        }

        float mx0 = -1e30f, mx1 = -1e30f;
#pragma unroll
        for (int j = 0; j < 8; j++) {
            mx0 = fmaxf(mx0, fmaxf(sc[j][0], sc[j][1]));
            mx1 = fmaxf(mx1, fmaxf(sc[j][2], sc[j][3]));
        }
        mx0 = fmaxf(mx0, __shfl_xor_sync(0xffffffff, mx0, 1));
        mx0 = fmaxf(mx0, __shfl_xor_sync(0xffffffff, mx0, 2));
        mx1 = fmaxf(mx1, __shfl_xor_sync(0xffffffff, mx1, 1));
        mx1 = fmaxf(mx1, __shfl_xor_sync(0xffffffff, mx1, 2));

        const float nm0 = fmaxf(mrun0, mx0);
        const float nm1 = fmaxf(mrun1, mx1);
        const float corr0 = __expf(mrun0 - nm0);
        const float corr1 = __expf(mrun1 - nm1);
        mrun0 = nm0; mrun1 = nm1;

        float sum0 = 0.f, sum1 = 0.f;
#pragma unroll
        for (int j = 0; j < 8; j++) {
            sc[j][0] = __expf(sc[j][0] - nm0); sum0 += sc[j][0];
            sc[j][1] = __expf(sc[j][1] - nm0); sum0 += sc[j][1];
            sc[j][2] = __expf(sc[j][2] - nm1); sum1 += sc[j][2];
            sc[j][3] = __expf(sc[j][3] - nm1); sum1 += sc[j][3];
        }
        sum0 += __shfl_xor_sync(0xffffffff, sum0, 1);
        sum0 += __shfl_xor_sync(0xffffffff, sum0, 2);
        sum1 += __shfl_xor_sync(0xffffffff, sum1, 1);
        sum1 += __shfl_xor_sync(0xffffffff, sum1, 2);
        lrun0 = lrun0 * corr0 + sum0;
        lrun1 = lrun1 * corr1 + sum1;

#pragma unroll
        for (int d = 0; d < 8; d++) {
            o[d][0] *= corr0; o[d][1] *= corr0;
            o[d][2] *= corr1; o[d][3] *= corr1;
        }

        uint32_t pa_h[4][4], pa_l[4][4];
#pragma unroll
        for (int kk2 = 0; kk2 < 4; kk2++) {
            const int jL = 2 * kk2, jH = 2 * kk2 + 1;
            pk2split_c(sc[jL][0], sc[jL][1], pa_h[kk2][0], pa_l[kk2][0]);
            pk2split_c(sc[jL][2], sc[jL][3], pa_h[kk2][1], pa_l[kk2][1]);
            pk2split_c(sc[jH][0], sc[jH][1], pa_h[kk2][2], pa_l[kk2][2]);
            pk2split_c(sc[jH][2], sc[jH][3], pa_h[kk2][3], pa_l[kk2][3]);
        }

#pragma unroll
        for (int kk2 = 0; kk2 < 4; kk2++) {
            uint32_t vbh[8][2], vbl[8][2];
#pragma unroll
            for (int e = 0; e < 4; e++) {
                uint32_t off = (uint32_t)(((kk2 * 16 + vRow) * DPAD) + e * 16 + vColH) * 2;
                LDSM4T(vbh[2*e][0], vbh[2*e][1], vbh[2*e+1][0], vbh[2*e+1][1], smV + off);
                LDSM4T(vbl[2*e][0], vbl[2*e][1], vbl[2*e+1][0], vbl[2*e+1][1], smVl + off);
            }
#pragma unroll
            for (int d = 0; d < 8; d++) {
                MMA16816(o[d], pa_h[kk2], vbh[d]);
                MMA16816(o[d], pa_h[kk2], vbl[d]);
                MMA16816(o[d], pa_l[kk2], vbh[d]);
            }
        }
        s ^= 1;
    }

    // ---- epilogue: write pre-split ctx planes ----
    const float inv0 = 1.f / lrun0;
    const float inv1 = 1.f / lrun1;
    const size_t c0 = ((size_t)(b * SEQ) + qrow0 + g) * HID + h * DK;
    const size_t c8 = c0 + 8 * HID;
#pragma unroll
    for (int d = 0; d < 8; d++) {
        const size_t off0 = c0 + d * 8 + 2 * tg;
        const size_t off8 = c8 + d * 8 + 2 * tg;
        __nv_bfloat16 h0, l0, h1, l1;
        bf16split(o[d][0] * inv0, h0, l0);
        bf16split(o[d][1] * inv0, h1, l1);
        *(__nv_bfloat162*)(g_ch + off0) = __nv_bfloat162(h0, h1);
        *(__nv_bfloat162*)(g_cl + off0) = __nv_bfloat162(l0, l1);
        bf16split(o[d][2] * inv1, h0, l0);
        bf16split(o[d][3] * inv1, h1, l1);
        *(__nv_bfloat162*)(g_ch + off8) = __nv_bfloat162(h0, h1);
        *(__nv_bfloat162*)(g_cl + off8) = __nv_bfloat162(l0, l1);
    }
}

// ---------------------------------------------------------------------------
extern "C" void kernel_launch(void* const* d_in, const int* in_sizes, int n_in,
                              void* d_out, int out_size)
{
    (void)in_sizes; (void)n_in; (void)out_size;
    const float* tgt = (const float*)d_in[0];
    const float* Wq  = (const float*)d_in[1];
    const float* bq  = (const float*)d_in[2];
    const float* Wk  = (const float*)d_in[3];
    const float* bk  = (const float*)d_in[4];
    const float* Wv  = (const float*)d_in[5];
    const float* bv  = (const float*)d_in[6];
    const float* Wo  = (const float*)d_in[7];
    const float* bo  = (const float*)d_in[8];
    float* out = (float*)d_out;

    cudaFuncSetAttribute(gemm_mma<0>, cudaFuncAttributeMaxDynamicSharedMemorySize, GEMM_SMEM);
    cudaFuncSetAttribute(gemm_mma<1>, cudaFuncAttributeMaxDynamicSharedMemorySize, GEMM_SMEM);
    cudaFuncSetAttribute(attn_mma,    cudaFuncAttributeMaxDynamicSharedMemorySize, ATTN_SMEM);

    // pre-pass splits (destinations resolved in device code)
    split_pre<0><<<(MTOT * HID / 4 + 255) / 256, 256>>>(tgt, MTOT * HID / 4);
    split_pre<1><<<(HID * HID / 4 + 255) / 256, 256>>>(Wq, HID * HID / 4);
    split_pre<2><<<(HID * HID / 4 + 255) / 256, 256>>>(Wk, HID * HID / 4);
    split_pre<3><<<(HID * HID / 4 + 255) / 256, 256>>>(Wv, HID * HID / 4);
    split_pre<4><<<(HID * HID / 4 + 255) / 256, 256>>>(Wo, HID * HID / 4);

    dim3 gQKV(MTOT / 128, HID / 128, 3);
    gemm_mma<0><<<gQKV, 256, GEMM_SMEM>>>(bq, bk, bv, nullptr);

    dim3 gATT(SEQ / QB, NH, BATCH);
    attn_mma<<<gATT, 256, ATTN_SMEM>>>();

    dim3 gOUT(MTOT / 128, HID / 128, 1);
    gemm_mma<1><<<gOUT, 256, GEMM_SMEM>>>(bo, nullptr, nullptr, out);
}

// round 15
// speedup vs baseline: 1.3562x; 1.1102x over previous
#include <cuda_runtime.h>
#include <cuda_bf16.h>
#include <cstdint>

#define HID   1024
#define NH    16
#define DK    64
#define BATCH 4
#define SEQ   2048
#define MTOT  (BATCH*SEQ)

// ---- mma.sync / ldmatrix / cp.async helpers ----
__device__ __forceinline__ uint32_t smem_to_u32(const void* p) {
    uint32_t a;
    asm("{ .reg .u64 t; cvta.to.shared.u64 t, %1; cvt.u32.u64 %0, t; }" : "=r"(a) : "l"(p));
    return a;
}
#define LDSM4(r0, r1, r2, r3, addr) \
    asm volatile("ldmatrix.sync.aligned.m8n8.x4.shared.b16 {%0,%1,%2,%3},[%4];" \
        : "=r"(r0), "=r"(r1), "=r"(r2), "=r"(r3) : "r"(addr))
#define LDSM4T(r0, r1, r2, r3, addr) \
    asm volatile("ldmatrix.sync.aligned.m8n8.x4.trans.shared.b16 {%0,%1,%2,%3},[%4];" \
        : "=r"(r0), "=r"(r1), "=r"(r2), "=r"(r3) : "r"(addr))
#define MMA16816(c, a, b) \
    asm volatile("mma.sync.aligned.m16n8k16.row.col.f32.bf16.bf16.f32 " \
        "{%0,%1,%2,%3},{%4,%5,%6,%7},{%8,%9},{%0,%1,%2,%3};" \
        : "+f"((c)[0]), "+f"((c)[1]), "+f"((c)[2]), "+f"((c)[3]) \
        : "r"((a)[0]), "r"((a)[1]), "r"((a)[2]), "r"((a)[3]), "r"((b)[0]), "r"((b)[1]))
#define CP_ASYNC16(dst, src) \
    asm volatile("cp.async.ca.shared.global [%0], [%1], 16;" :: "r"(dst), "l"(src) : "memory")
#define CP_COMMIT()  asm volatile("cp.async.commit_group;" ::: "memory")
#define CP_WAIT0()   asm volatile("cp.async.wait_group 0;" ::: "memory")

// bf16 2-term split helpers
__device__ __forceinline__ void bf16split(float x, __nv_bfloat16& h, __nv_bfloat16& l) {
    h = __float2bfloat16_rn(x);
    l = __float2bfloat16_rn(x - __bfloat162float(h));
}
__device__ __forceinline__ uint32_t pkbf(__nv_bfloat16 a, __nv_bfloat16 b) {
    __nv_bfloat162 t(a, b);
    return *(uint32_t*)&t;
}
__device__ __forceinline__ void pk2split_c(float x, float y, uint32_t& h, uint32_t& l) {
    __nv_bfloat16 hx, lx, hy, ly;
    bf16split(x, hx, lx); bf16split(y, hy, ly);
    h = pkbf(hx, hy); l = pkbf(lx, ly);
}

// Scratch (allocation-free rule: __device__ globals)
__device__ float g_q[(size_t)BATCH*NH*SEQ*DK];           // fp32, pre-scaled by 1/8
__device__ __nv_bfloat16 g_kh[(size_t)BATCH*NH*SEQ*DK];
__device__ __nv_bfloat16 g_kl[(size_t)BATCH*NH*SEQ*DK];
__device__ __nv_bfloat16 g_vh[(size_t)BATCH*NH*SEQ*DK];
__device__ __nv_bfloat16 g_vl[(size_t)BATCH*NH*SEQ*DK];
// pre-split operand planes
__device__ __nv_bfloat16 g_xh[(size_t)MTOT*HID], g_xl[(size_t)MTOT*HID];    // tgt
__device__ __nv_bfloat16 g_ch[(size_t)MTOT*HID], g_cl[(size_t)MTOT*HID];    // ctx
__device__ __nv_bfloat16 g_wqh[(size_t)HID*HID], g_wql[(size_t)HID*HID];
__device__ __nv_bfloat16 g_wkh[(size_t)HID*HID], g_wkl[(size_t)HID*HID];
__device__ __nv_bfloat16 g_wvh[(size_t)HID*HID], g_wvl[(size_t)HID*HID];
__device__ __nv_bfloat16 g_woh[(size_t)HID*HID], g_wol[(size_t)HID*HID];

// ---------------------------------------------------------------------------
// Pre-pass: fp32 -> bf16 hi/lo planes. Destination selected by template.
// ---------------------------------------------------------------------------
template<int WHICH>
__global__ void split_pre(const float* __restrict__ src, int n4)
{
    __nv_bfloat16* dh;
    __nv_bfloat16* dl;
    if      (WHICH == 0) { dh = g_xh;  dl = g_xl;  }
    else if (WHICH == 1) { dh = g_wqh; dl = g_wql; }
    else if (WHICH == 2) { dh = g_wkh; dl = g_wkl; }
    else if (WHICH == 3) { dh = g_wvh; dl = g_wvl; }
    else                 { dh = g_woh; dl = g_wol; }

    int i = blockIdx.x * blockDim.x + threadIdx.x;
    if (i >= n4) return;
    float4 v = ((const float4*)src)[i];
    __nv_bfloat16 h0, l0, h1, l1, h2, l2, h3, l3;
    bf16split(v.x, h0, l0); bf16split(v.y, h1, l1);
    bf16split(v.z, h2, l2); bf16split(v.w, h3, l3);
    uint2 hv, lv;
    hv.x = pkbf(h0, h1); hv.y = pkbf(h2, h3);
    lv.x = pkbf(l0, l1); lv.y = pkbf(l2, l3);
    ((uint2*)dh)[i] = hv;
    ((uint2*)dl)[i] = lv;
}

// ---------------------------------------------------------------------------
// bf16-split tensor-core GEMM, attention-shaped pipeline:
// BK=64, 2-stage cp.async depth-1 (wait-all), ONE sync per k-iter.
// Y = X W^T + bias.
// MODE 0: X=g_xh/l, W per z -> g_q (scaled) / g_kh,kl / g_vh,vl
// MODE 1: X=g_ch/l, W=g_woh/l -> OutPlain
// ---------------------------------------------------------------------------
#define BK      64
#define NKT     (HID / BK)         // 16
#define KPAD    72                 // 144B pitch (validated in attention)
#define PLANEB  (128 * KPAD * 2)   // 18432 bytes
#define STGB    (4 * PLANEB)       // 73728 bytes per stage
#define GEMM_SMEM (2 * STGB)       // 147456

template<int MODE>
__global__ __launch_bounds__(256)
void gemm_mma(const float* __restrict__ Bq,
              const float* __restrict__ Bk,
              const float* __restrict__ Bv,
              float* __restrict__ OutPlain)
{
    extern __shared__ __nv_bfloat16 sm[];
    const uint32_t smb = smem_to_u32(sm);

    const int z = blockIdx.z;
    const __nv_bfloat16* pAh = (MODE == 0) ? g_xh : g_ch;
    const __nv_bfloat16* pAl = (MODE == 0) ? g_xl : g_cl;
    const __nv_bfloat16* pBh;
    const __nv_bfloat16* pBl;
    const float* bias;
    if (MODE == 0) {
        pBh  = (z == 0) ? g_wqh : ((z == 1) ? g_wkh : g_wvh);
        pBl  = (z == 0) ? g_wql : ((z == 1) ? g_wkl : g_wvl);
        bias = (z == 0) ? Bq : ((z == 1) ? Bk : Bv);
    } else {
        pBh = g_woh; pBl = g_wol; bias = Bq;
    }

    const int m0   = blockIdx.x * 128;
    const int n0   = blockIdx.y * 128;
    const int tid  = threadIdx.x;
    const int wid  = tid >> 5;
    const int lane = tid & 31;
    const int warp_m = (wid >> 2) * 64;
    const int warp_n = (wid & 3) * 32;

    // cp.async staging: 4 planes x 128 rows x 8 chunks(16B) = 4096, 16/thread
    auto prefetch = [&](int kt, int s) {
        const uint32_t dstStage = smb + (uint32_t)s * STGB;
#pragma unroll
        for (int t = 0; t < 16; t++) {
            const int plane = t >> 2;                 // 0=Ah 1=Al 2=Bh 3=Bl
            const int inner = ((t & 3) << 8) + tid;   // 0..1023
            const int r  = inner >> 3;                // 0..127
            const int c8 = inner & 7;                 // 0..7
            const uint32_t dst = dstStage + (uint32_t)plane * PLANEB + r * (KPAD * 2) + c8 * 16;
            const __nv_bfloat16* src =
                (plane == 0 ? pAh + (size_t)(m0 + r) * HID :
                 plane == 1 ? pAl + (size_t)(m0 + r) * HID :
                 plane == 2 ? pBh + (size_t)(n0 + r) * HID :
                              pBl + (size_t)(n0 + r) * HID) + kt * BK + c8 * 8;
            CP_ASYNC16(dst, src);
        }
        CP_COMMIT();
    };

    float acc[4][4][4];
#pragma unroll
    for (int mt = 0; mt < 4; mt++)
#pragma unroll
        for (int nt = 0; nt < 4; nt++)
#pragma unroll
            for (int e = 0; e < 4; e++) acc[mt][nt][e] = 0.f;

    const int arow = warp_m + (lane & 15);
    const int acolL = (lane >> 4) * 8;
    const int brow = warp_n + ((lane >> 4) & 1) * 8 + (lane & 7);
    const int bcolL = ((lane >> 3) & 1) * 8;

    prefetch(0, 0);

    for (int kt = 0; kt < NKT; kt++) {
        CP_WAIT0();
        __syncthreads();
        if (kt + 1 < NKT) prefetch(kt + 1, (kt + 1) & 1);

        const uint32_t sb = smb + (uint32_t)((kt & 1) * STGB);
        uint32_t ahi[4][4], alo[4][4], bhi[4][2], blo[4][2];
#pragma unroll
        for (int sub = 0; sub < 4; sub++) {
            const int kks = sub * 16;
#pragma unroll
            for (int mt = 0; mt < 4; mt++) {
                uint32_t ad = sb + (uint32_t)(((arow + mt * 16) * KPAD) + kks + acolL) * 2;
                LDSM4(ahi[mt][0], ahi[mt][1], ahi[mt][2], ahi[mt][3], ad);
                LDSM4(alo[mt][0], alo[mt][1], alo[mt][2], alo[mt][3], ad + PLANEB);
            }
#pragma unroll
            for (int p = 0; p < 2; p++) {
                uint32_t bd = sb + (uint32_t)(2 * PLANEB) +
                              (uint32_t)(((brow + p * 16) * KPAD) + kks + bcolL) * 2;
                LDSM4(bhi[2*p][0], bhi[2*p][1], bhi[2*p+1][0], bhi[2*p+1][1], bd);
                LDSM4(blo[2*p][0], blo[2*p][1], blo[2*p+1][0], blo[2*p+1][1], bd + PLANEB);
            }
#pragma unroll
            for (int mt = 0; mt < 4; mt++)
#pragma unroll
                for (int nt = 0; nt < 4; nt++) {
                    MMA16816(acc[mt][nt], ahi[mt], bhi[nt]);
                    MMA16816(acc[mt][nt], ahi[mt], blo[nt]);
                    MMA16816(acc[mt][nt], alo[mt], bhi[nt]);
                }
        }
        // no trailing sync: next iter's leading __syncthreads (after CP_WAIT0)
        // orders all warps' reads of this stage before it is overwritten.
    }

    const int g  = lane >> 2;
    const int tg = lane & 3;
#pragma unroll
    for (int mt = 0; mt < 4; mt++) {
        const int m1 = m0 + warp_m + mt * 16 + g;
        const int m2 = m1 + 8;
#pragma unroll
        for (int nt = 0; nt < 4; nt++) {
            const int n = n0 + warp_n + nt * 8 + tg * 2;
            const float bv0 = __ldg(bias + n);
            const float bv1 = __ldg(bias + n + 1);
            const float* c = acc[mt][nt];
            if (MODE == 0) {
                const int hh = n >> 6, d = n & 63;
                const size_t i1 = (((size_t)((m1 >> 11) * NH + hh)) * SEQ + (m1 & 2047)) * DK + d;
                const size_t i2 = (((size_t)((m2 >> 11) * NH + hh)) * SEQ + (m2 & 2047)) * DK + d;
                const float v0 = c[0] + bv0, v1 = c[1] + bv1;
                const float v2 = c[2] + bv0, v3 = c[3] + bv1;
                if (z == 0) {
                    *(float2*)(g_q + i1) = make_float2(v0 * 0.125f, v1 * 0.125f);
                    *(float2*)(g_q + i2) = make_float2(v2 * 0.125f, v3 * 0.125f);
                } else {
                    __nv_bfloat16* ph = (z == 1) ? g_kh : g_vh;
                    __nv_bfloat16* pl = (z == 1) ? g_kl : g_vl;
                    __nv_bfloat16 h0, l0, h1, l1;
                    bf16split(v0, h0, l0); bf16split(v1, h1, l1);
                    *(__nv_bfloat162*)(ph + i1) = __nv_bfloat162(h0, h1);
                    *(__nv_bfloat162*)(pl + i1) = __nv_bfloat162(l0, l1);
                    bf16split(v2, h0, l0); bf16split(v3, h1, l1);
                    *(__nv_bfloat162*)(ph + i2) = __nv_bfloat162(h0, h1);
                    *(__nv_bfloat162*)(pl + i2) = __nv_bfloat162(l0, l1);
                }
            } else {
                *(float2*)(OutPlain + (size_t)m1 * HID + n) = make_float2(c[0] + bv0, c[1] + bv1);
                *(float2*)(OutPlain + (size_t)m2 * HID + n) = make_float2(c[2] + bv0, c[3] + bv1);
            }
        }
    }
}

// ---------------------------------------------------------------------------
// Flash attention on tensor cores (validated R10/R14, unchanged).
// ---------------------------------------------------------------------------
#define SC    64
#define QB    128
#define DPAD  72
#define PLB   (SC * DPAD * 2)
#define ATTN_SMEM (2 * 4 * PLB)

__global__ __launch_bounds__(256)
void attn_mma()
{
    extern __shared__ __nv_bfloat16 asmem[];
    const uint32_t smBase = smem_to_u32(asmem);

    const int b    = blockIdx.z;
    const int h    = blockIdx.y;
    const int tid  = threadIdx.x;
    const int wid  = tid >> 5;
    const int lane = tid & 31;
    const int g    = lane >> 2;
    const int tg   = lane & 3;

    const size_t bh = (size_t)(b * NH + h);
    const size_t bhoff = bh * SEQ * DK;
    const int qrow0 = blockIdx.x * QB + wid * 16;

    uint32_t qa_h[4][4], qa_l[4][4];
    {
        const float* q0 = g_q + (bh * SEQ + qrow0 + g) * DK;
        const float* q8 = q0 + 8 * DK;
#pragma unroll
        for (int kk = 0; kk < 4; kk++) {
            float2 v;
            v = *(const float2*)(q0 + kk * 16 + 2 * tg);
            pk2split_c(v.x, v.y, qa_h[kk][0], qa_l[kk][0]);
            v = *(const float2*)(q8 + kk * 16 + 2 * tg);
            pk2split_c(v.x, v.y, qa_h[kk][1], qa_l[kk][1]);
            v = *(const float2*)(q0 + kk * 16 + 8 + 2 * tg);
            pk2split_c(v.x, v.y, qa_h[kk][2], qa_l[kk][2]);
            v = *(const float2*)(q8 + kk * 16 + 8 + 2 * tg);
            pk2split_c(v.x, v.y, qa_h[kk][3], qa_l[kk][3]);
        }
    }

    float o[8][4];
#pragma unroll
    for (int d = 0; d < 8; d++)
#pragma unroll
        for (int e = 0; e < 4; e++) o[d][e] = 0.f;
    float mrun0 = -1e30f, mrun1 = -1e30f, lrun0 = 0.f, lrun1 = 0.f;

    auto prefetch = [&](int kc, int s) {
        const uint32_t dstStage = smBase + (uint32_t)s * 4 * PLB;
#pragma unroll
        for (int t = 0; t < 8; t++) {
            const int plane = t >> 1;
            const int inner = ((t & 1) << 8) + tid;
            const int r  = inner >> 3;
            const int c8 = inner & 7;
            const uint32_t dst = dstStage + (uint32_t)plane * PLB + r * (DPAD * 2) + c8 * 16;
            const __nv_bfloat16* src =
                (plane == 0 ? g_kh : plane == 1 ? g_kl : plane == 2 ? g_vh : g_vl)
                + bhoff + (size_t)(kc + r) * DK + c8 * 8;
            CP_ASYNC16(dst, src);
        }
        CP_COMMIT();
    };

    const int kRow = ((lane >> 4) & 1) * 8 + (lane & 7);
    const int kColH = ((lane >> 3) & 1) * 8;
    const int vRow = ((lane >> 3) & 1) * 8 + (lane & 7);
    const int vColH = (lane >> 4) * 8;

    int s = 0;
    prefetch(0, 0);

    for (int kc = 0; kc < SEQ; kc += SC) {
        CP_WAIT0();
        __syncthreads();
        if (kc + SC < SEQ) prefetch(kc + SC, s ^ 1);

        const uint32_t stage = smBase + (uint32_t)s * 4 * PLB;
        const uint32_t smK  = stage;
        const uint32_t smKl = stage + PLB;
        const uint32_t smV  = stage + 2 * PLB;
        const uint32_t smVl = stage + 3 * PLB;

        float sc[8][4];
#pragma unroll
        for (int j = 0; j < 8; j++)
#pragma unroll
            for (int e = 0; e < 4; e++) sc[j][e] = 0.f;

#pragma unroll
        for (int kk = 0; kk < 4; kk++) {
            uint32_t kbh[8][2], kbl[8][2];
#pragma unroll
            for (int p = 0; p < 4; p++) {
                uint32_t off = (uint32_t)(((p * 16 + kRow) * DPAD) + kk * 16 + kColH) * 2;
                LDSM4(kbh[2*p][0], kbh[2*p][1], kbh[2*p+1][0], kbh[2*p+1][1], smK + off);
                LDSM4(kbl[2*p][0], kbl[2*p][1], kbl[2*p+1][0], kbl[2*p+1][1], smKl + off);
            }
#pragma unroll
            for (int j = 0; j < 8; j++) {
                MMA16816(sc[j], qa_h[kk], kbh[j]);
                MMA16816(sc[j], qa_h[kk], kbl[j]);
                MMA16816(sc[j], qa_l[kk], kbh[j]);
            }
        }

        float mx0 = -1e30f, mx1 = -1e30f;
#pragma unroll
        for (int j = 0; j < 8; j++) {
            mx0 = fmaxf(mx0, fmaxf(sc[j][0], sc[j][1]));
            mx1 = fmaxf(mx1, fmaxf(sc[j][2], sc[j][3]));
        }
        mx0 = fmaxf(mx0, __shfl_xor_sync(0xffffffff, mx0, 1));
        mx0 = fmaxf(mx0, __shfl_xor_sync(0xffffffff, mx0, 2));
        mx1 = fmaxf(mx1, __shfl_xor_sync(0xffffffff, mx1, 1));
        mx1 = fmaxf(mx1, __shfl_xor_sync(0xffffffff, mx1, 2));

        const float nm0 = fmaxf(mrun0, mx0);
        const float nm1 = fmaxf(mrun1, mx1);
        const float corr0 = __expf(mrun0 - nm0);
        const float corr1 = __expf(mrun1 - nm1);
        mrun0 = nm0; mrun1 = nm1;

        float sum0 = 0.f, sum1 = 0.f;
#pragma unroll
        for (int j = 0; j < 8; j++) {
            sc[j][0] = __expf(sc[j][0] - nm0); sum0 += sc[j][0];
            sc[j][1] = __expf(sc[j][1] - nm0); sum0 += sc[j][1];
            sc[j][2] = __expf(sc[j][2] - nm1); sum1 += sc[j][2];
            sc[j][3] = __expf(sc[j][3] - nm1); sum1 += sc[j][3];
        }
        sum0 += __shfl_xor_sync(0xffffffff, sum0, 1);
        sum0 += __shfl_xor_sync(0xffffffff, sum0, 2);
        sum1 += __shfl_xor_sync(0xffffffff, sum1, 1);
        sum1 += __shfl_xor_sync(0xffffffff, sum1, 2);
        lrun0 = lrun0 * corr0 + sum0;
        lrun1 = lrun1 * corr1 + sum1;

#pragma unroll
        for (int d = 0; d < 8; d++) {
            o[d][0] *= corr0; o[d][1] *= corr0;
            o[d][2] *= corr1; o[d][3] *= corr1;
        }

        uint32_t pa_h[4][4], pa_l[4][4];
#pragma unroll
        for (int kk2 = 0; kk2 < 4; kk2++) {
            const int jL = 2 * kk2, jH = 2 * kk2 + 1;
            pk2split_c(sc[jL][0], sc[jL][1], pa_h[kk2][0], pa_l[kk2][0]);
            pk2split_c(sc[jL][2], sc[jL][3], pa_h[kk2][1], pa_l[kk2][1]);
            pk2split_c(sc[jH][0], sc[jH][1], pa_h[kk2][2], pa_l[kk2][2]);
            pk2split_c(sc[jH][2], sc[jH][3], pa_h[kk2][3], pa_l[kk2][3]);
        }

#pragma unroll
        for (int kk2 = 0; kk2 < 4; kk2++) {
            uint32_t vbh[8][2], vbl[8][2];
#pragma unroll
            for (int e = 0; e < 4; e++) {
                uint32_t off = (uint32_t)(((kk2 * 16 + vRow) * DPAD) + e * 16 + vColH) * 2;
                LDSM4T(vbh[2*e][0], vbh[2*e][1], vbh[2*e+1][0], vbh[2*e+1][1], smV + off);
                LDSM4T(vbl[2*e][0], vbl[2*e][1], vbl[2*e+1][0], vbl[2*e+1][1], smVl + off);
            }
#pragma unroll
            for (int d = 0; d < 8; d++) {
                MMA16816(o[d], pa_h[kk2], vbh[d]);
                MMA16816(o[d], pa_h[kk2], vbl[d]);
                MMA16816(o[d], pa_l[kk2], vbh[d]);
            }
        }
        s ^= 1;
    }

    // ---- epilogue: write pre-split ctx planes ----
    const float inv0 = 1.f / lrun0;
    const float inv1 = 1.f / lrun1;
    const size_t c0 = ((size_t)(b * SEQ) + qrow0 + g) * HID + h * DK;
    const size_t c8 = c0 + 8 * HID;
#pragma unroll
    for (int d = 0; d < 8; d++) {
        const size_t off0 = c0 + d * 8 + 2 * tg;
        const size_t off8 = c8 + d * 8 + 2 * tg;
        __nv_bfloat16 h0, l0, h1, l1;
        bf16split(o[d][0] * inv0, h0, l0);
        bf16split(o[d][1] * inv0, h1, l1);
        *(__nv_bfloat162*)(g_ch + off0) = __nv_bfloat162(h0, h1);
        *(__nv_bfloat162*)(g_cl + off0) = __nv_bfloat162(l0, l1);
        bf16split(o[d][2] * inv1, h0, l0);
        bf16split(o[d][3] * inv1, h1, l1);
        *(__nv_bfloat162*)(g_ch + off8) = __nv_bfloat162(h0, h1);
        *(__nv_bfloat162*)(g_cl + off8) = __nv_bfloat162(l0, l1);
    }
}

// ---------------------------------------------------------------------------
extern "C" void kernel_launch(void* const* d_in, const int* in_sizes, int n_in,
                              void* d_out, int out_size)
{
    (void)in_sizes; (void)n_in; (void)out_size;
    const float* tgt = (const float*)d_in[0];
    const float* Wq  = (const float*)d_in[1];
    const float* bq  = (const float*)d_in[2];
    const float* Wk  = (const float*)d_in[3];
    const float* bk  = (const float*)d_in[4];
    const float* Wv  = (const float*)d_in[5];
    const float* bv  = (const float*)d_in[6];
    const float* Wo  = (const float*)d_in[7];
    const float* bo  = (const float*)d_in[8];
    float* out = (float*)d_out;

    cudaFuncSetAttribute(gemm_mma<0>, cudaFuncAttributeMaxDynamicSharedMemorySize, GEMM_SMEM);
    cudaFuncSetAttribute(gemm_mma<1>, cudaFuncAttributeMaxDynamicSharedMemorySize, GEMM_SMEM);
    cudaFuncSetAttribute(attn_mma,    cudaFuncAttributeMaxDynamicSharedMemorySize, ATTN_SMEM);

    // pre-pass splits (destinations resolved in device code)
    split_pre<0><<<(MTOT * HID / 4 + 255) / 256, 256>>>(tgt, MTOT * HID / 4);
    split_pre<1><<<(HID * HID / 4 + 255) / 256, 256>>>(Wq, HID * HID / 4);
    split_pre<2><<<(HID * HID / 4 + 255) / 256, 256>>>(Wk, HID * HID / 4);
    split_pre<3><<<(HID * HID / 4 + 255) / 256, 256>>>(Wv, HID * HID / 4);
    split_pre<4><<<(HID * HID / 4 + 255) / 256, 256>>>(Wo, HID * HID / 4);

    dim3 gQKV(MTOT / 128, HID / 128, 3);
    gemm_mma<0><<<gQKV, 256, GEMM_SMEM>>>(bq, bk, bv, nullptr);

    dim3 gATT(SEQ / QB, NH, BATCH);
    attn_mma<<<gATT, 256, ATTN_SMEM>>>();

    dim3 gOUT(MTOT / 128, HID / 128, 1);
    gemm_mma<1><<<gOUT, 256, GEMM_SMEM>>>(bo, nullptr, nullptr, out);
}